// round 16
// baseline (speedup 1.0000x reference)
#include <cuda_runtime.h>
#include <cuda_fp16.h>
#include <cstdint>

// ---------------------------------------------------------------------------
// Problem constants
// ---------------------------------------------------------------------------
static constexpr int E_  = 8;
static constexpr int H_  = 1024;
static constexpr int FF_ = 4096;
static constexpr int T_  = 32768;
static constexpr int G_  = T_ / E_;     // 4096 tokens per expert

// GEMM tiling: CTA 128x128, 4 warps (2 M x 2 N), warp tile 64x64, BK=32
// 128 threads -> 255 regs available AND 2 CTAs/SM (32K regs/CTA = half RF).
// 64x64 warp tiles cut ldsm crossbar duplication to 2xA + 2xB = 32KB/stage
// (vs 48KB for 8-warp grids) - crossbar was the measured co-limiter.
static constexpr int BM = 128;
static constexpr int BN = 128;
static constexpr int BK = 32;           // fp16 elems per K-stage
static constexpr int PITCH = 80;        // SMEM row pitch bytes (64B data + 16B pad)
static constexpr int OFF_B = BM * PITCH;                  // 10240
static constexpr int STAGE_BYTES = OFF_B + BN * PITCH;    // 20480
static constexpr int NSTAGE = 3;
static constexpr int SMEM_TOTAL = NSTAGE * STAGE_BYTES;   // 61440 (2 CTAs = 120KB)
static constexpr int NTHREADS = 128;

// ---------------------------------------------------------------------------
// Device scratch
// ---------------------------------------------------------------------------
__device__ __half g_XH[(size_t)T_ * H_];
__device__ __half g_W1H[(size_t)E_ * FF_ * H_];
__device__ __half g_W2TH[(size_t)E_ * H_ * FF_];
__device__ __half g_HH[(size_t)T_ * FF_];

// ---------------------------------------------------------------------------
// PTX helpers (family-safe: sm_80-era instructions only)
// ---------------------------------------------------------------------------
__device__ __forceinline__ uint32_t smem_u32(const void* p) {
    uint32_t a;
    asm("{ .reg .u64 t; cvta.to.shared.u64 t, %1; cvt.u32.u64 %0, t; }" : "=r"(a) : "l"(p));
    return a;
}
__device__ __forceinline__ void cp16(uint32_t dst, const void* src) {
    asm volatile("cp.async.cg.shared.global [%0], [%1], 16;" :: "r"(dst), "l"(src) : "memory");
}
#define CP_COMMIT() asm volatile("cp.async.commit_group;" ::: "memory")
#define CP_WAIT2()  asm volatile("cp.async.wait_group 2;" ::: "memory")

__device__ __forceinline__ void ldsm4(uint32_t& r0, uint32_t& r1, uint32_t& r2, uint32_t& r3,
                                      uint32_t addr) {
    asm volatile("ldmatrix.sync.aligned.m8n8.x4.shared.b16 {%0,%1,%2,%3}, [%4];"
                 : "=r"(r0), "=r"(r1), "=r"(r2), "=r"(r3) : "r"(addr));
}
__device__ __forceinline__ void mma16816(float* d, const uint32_t* a, const uint32_t* b) {
    asm volatile(
        "mma.sync.aligned.m16n8k16.row.col.f32.f16.f16.f32 "
        "{%0,%1,%2,%3}, {%4,%5,%6,%7}, {%8,%9}, {%0,%1,%2,%3};"
        : "+f"(d[0]), "+f"(d[1]), "+f"(d[2]), "+f"(d[3])
        : "r"(a[0]), "r"(a[1]), "r"(a[2]), "r"(a[3]), "r"(b[0]), "r"(b[1]));
}

__device__ __forceinline__ uint32_t pack2h(__half a, __half b) {
    __half2 p = __halves2half2(a, b);
    return *reinterpret_cast<uint32_t*>(&p);
}

// ---------------------------------------------------------------------------
// fp32 -> fp16 cast kernels
// ---------------------------------------------------------------------------
__global__ void tohalf_kernel(const float* __restrict__ in,
                              __half* __restrict__ out, int n4) {
    for (int i = blockIdx.x * blockDim.x + threadIdx.x; i < n4; i += gridDim.x * blockDim.x) {
        float4 v = reinterpret_cast<const float4*>(in)[i];
        uint2 p;
        p.x = pack2h(__float2half(v.x), __float2half(v.y));
        p.y = pack2h(__float2half(v.z), __float2half(v.w));
        reinterpret_cast<uint2*>(out)[i] = p;
    }
}

// w2 [E, FF, H] -> w2t [E, H, FF] fp16, 32x32 SMEM tile transpose
__global__ void transpose_half(const float* __restrict__ in,
                               __half* __restrict__ outh) {
    __shared__ float t[32][33];
    const int e  = blockIdx.z;
    const int h0 = blockIdx.x * 32;
    const int f0 = blockIdx.y * 32;
    const float* src = in + (size_t)e * FF_ * H_;
#pragma unroll
    for (int j = 0; j < 4; j++)
        t[threadIdx.y + j * 8][threadIdx.x] =
            src[(size_t)(f0 + threadIdx.y + j * 8) * H_ + h0 + threadIdx.x];
    __syncthreads();
    __half* dh = outh + (size_t)e * H_ * FF_;
#pragma unroll
    for (int j = 0; j < 4; j++) {
        float v = t[threadIdx.x][threadIdx.y + j * 8];
        dh[(size_t)(h0 + threadIdx.y + j * 8) * FF_ + f0 + threadIdx.x] = __float2half(v);
    }
}

// ---------------------------------------------------------------------------
// TN grouped GEMM: C[M,N] = A[M,K] @ B[N,K]^T, fp16 single-term, fp32 accum.
// CTA tile 128x128; 4 warps as 2(M) x 2(N); warp tile 64x64; mma m16n8k16.
// MODE 0: epilogue = relu -> fp16 store into Hc (pitch FF_)
// MODE 1: epilogue = fp32 store into Cf (pitch H_)
// ---------------------------------------------------------------------------
template <int KDIM, int MODE>
__global__ void __launch_bounds__(NTHREADS, 2)
gemm_h1(const __half* __restrict__ A, int lda,
        const __half* __restrict__ B, int ldb, int bExpStride,
        __half* __restrict__ Hc, float* __restrict__ Cf) {
    extern __shared__ char smem[];
    const uint32_t sbase = smem_u32(smem);
    const int tid  = threadIdx.x;
    const int lane = tid & 31;
    const int warp = tid >> 5;
    const int wm = warp & 1;           // 0..1 (M, 64 rows each)
    const int wn = warp >> 1;          // 0..1 (N, 64 cols each)
    const int aRow0 = blockIdx.z * G_ + blockIdx.y * BM;
    const int bRow0 = blockIdx.z * bExpStride + blockIdx.x * BN;
    const int col0  = blockIdx.x * BN;
    constexpr int S = KDIM / BK;

    float acc[4][8][4];
#pragma unroll
    for (int i = 0; i < 4; i++)
#pragma unroll
        for (int j = 0; j < 8; j++)
#pragma unroll
            for (int q = 0; q < 4; q++) acc[i][j][q] = 0.f;

    // stage loader: A 512 chunks(16B), B 512 chunks -> 8 cp16/thread
    auto load_stage = [&](int s, int buf) {
        const uint32_t st = sbase + buf * STAGE_BYTES;
        const int k0 = s * BK;
#pragma unroll
        for (int i = 0; i < 4; i++) {
            int c = tid + i * NTHREADS;
            int r = c >> 2, q = c & 3;
            uint32_t so = (uint32_t)(r * PITCH + q * 16);
            cp16(st + so,         A + (size_t)(aRow0 + r) * lda + k0 + q * 8);
            cp16(st + OFF_B + so, B + (size_t)(bRow0 + r) * ldb + k0 + q * 8);
        }
    };

    // lane-fixed parts of ldmatrix addresses
    const uint32_t aLane = (uint32_t)((wm * 64 + (lane & 15)) * PITCH + (lane >> 4) * 16);
    const uint32_t bLane = (uint32_t)((wn * 64 + (lane & 15)) * PITCH + (lane >> 4) * 16);

    load_stage(0, 0); CP_COMMIT();
    load_stage(1, 1); CP_COMMIT();

    for (int s = 0; s < S; s++) {
        if (s + 2 < S) load_stage(s + 2, (s + 2) % NSTAGE);
        CP_COMMIT();
        CP_WAIT2();
        __syncthreads();

        const uint32_t st = sbase + (s % NSTAGE) * STAGE_BYTES;
#pragma unroll
        for (int ks = 0; ks < 2; ks++) {               // two k16 steps per stage
            const uint32_t kOff = (uint32_t)(ks * 32); // 16 elems * 2B
            uint32_t ah[4][4], bx[8][2];
#pragma unroll
            for (int i = 0; i < 4; i++) {
                uint32_t ad = st + aLane + kOff + (uint32_t)(i * 16 * PITCH);
                ldsm4(ah[i][0], ah[i][1], ah[i][2], ah[i][3], ad);
            }
#pragma unroll
            for (int jj = 0; jj < 4; jj++) {
                uint32_t bd = st + OFF_B + bLane + kOff + (uint32_t)(jj * 16 * PITCH);
                uint32_t r0, r1, r2, r3;
                ldsm4(r0, r1, r2, r3, bd);
                bx[jj * 2 + 0][0] = r0; bx[jj * 2 + 1][0] = r1;
                bx[jj * 2 + 0][1] = r2; bx[jj * 2 + 1][1] = r3;
            }
#pragma unroll
            for (int i = 0; i < 4; i++)
#pragma unroll
                for (int j = 0; j < 8; j++) mma16816(acc[i][j], ah[i], bx[j]);
        }
        __syncthreads();
    }

    // ---- epilogue (register -> global) ------------------------------------
    const int rBase = aRow0 + wm * 64 + (lane >> 2);
    const int cBase = col0 + wn * 64 + 2 * (lane & 3);
    if (MODE == 0) {
        uint32_t* gH = reinterpret_cast<uint32_t*>(Hc);
#pragma unroll
        for (int i = 0; i < 4; i++)
#pragma unroll
            for (int j = 0; j < 8; j++) {
                int r0 = rBase + i * 16;
                int c  = cBase + j * 8;
                float v0 = fmaxf(acc[i][j][0], 0.f), v1 = fmaxf(acc[i][j][1], 0.f);
                float v2 = fmaxf(acc[i][j][2], 0.f), v3 = fmaxf(acc[i][j][3], 0.f);
                size_t w0 = ((size_t)r0 * FF_ + c) >> 1;
                size_t w1 = ((size_t)(r0 + 8) * FF_ + c) >> 1;
                gH[w0] = pack2h(__float2half(v0), __float2half(v1));
                gH[w1] = pack2h(__float2half(v2), __float2half(v3));
            }
    } else {
#pragma unroll
        for (int i = 0; i < 4; i++)
#pragma unroll
            for (int j = 0; j < 8; j++) {
                int r0 = rBase + i * 16;
                int c  = cBase + j * 8;
                float2 p0 = make_float2(acc[i][j][0], acc[i][j][1]);
                float2 p1 = make_float2(acc[i][j][2], acc[i][j][3]);
                *reinterpret_cast<float2*>(&Cf[(size_t)r0 * H_ + c])       = p0;
                *reinterpret_cast<float2*>(&Cf[(size_t)(r0 + 8) * H_ + c]) = p1;
            }
    }
}

// ---------------------------------------------------------------------------
// Host launcher
// ---------------------------------------------------------------------------
extern "C" void kernel_launch(void* const* d_in, const int* in_sizes, int n_in,
                              void* d_out, int out_size) {
    (void)in_sizes; (void)n_in; (void)out_size;
    const float* x  = (const float*)d_in[0];
    const float* w1 = (const float*)d_in[1];
    const float* w2 = (const float*)d_in[2];
    float* out = (float*)d_out;

    void *xh, *w1h, *w2th, *hh;
    cudaGetSymbolAddress(&xh,  g_XH);
    cudaGetSymbolAddress(&w1h, g_W1H);
    cudaGetSymbolAddress(&w2th, g_W2TH);
    cudaGetSymbolAddress(&hh,  g_HH);

    cudaFuncSetAttribute(gemm_h1<1024, 0>,
                         cudaFuncAttributeMaxDynamicSharedMemorySize, SMEM_TOTAL);
    cudaFuncSetAttribute(gemm_h1<4096, 1>,
                         cudaFuncAttributeMaxDynamicSharedMemorySize, SMEM_TOTAL);

    // 1) fp32 -> fp16 casts
    tohalf_kernel<<<2048, 256>>>(x, (__half*)xh, T_ * H_ / 4);
    tohalf_kernel<<<2048, 256>>>(w1, (__half*)w1h, E_ * FF_ * H_ / 4);
    transpose_half<<<dim3(H_ / 32, FF_ / 32, E_), dim3(32, 8)>>>(w2, (__half*)w2th);

    // 2) GEMM1: h = relu(x @ w1^T) -> fp16; A ld=H, B ld=H, expert stride FF
    gemm_h1<1024, 0><<<dim3(FF_ / BN, G_ / BM, E_), NTHREADS, SMEM_TOTAL>>>(
        (const __half*)xh, H_,
        (const __half*)w1h, H_, FF_,
        (__half*)hh, nullptr);

    // 3) GEMM2: out = h @ w2 (w2 pre-transposed -> TN); A ld=FF, B ld=FF, stride H
    gemm_h1<4096, 1><<<dim3(H_ / BN, G_ / BM, E_), NTHREADS, SMEM_TOTAL>>>(
        (const __half*)hh, FF_,
        (const __half*)w2th, FF_, H_,
        nullptr, out);
}

// round 17
// speedup vs baseline: 1.1627x; 1.1627x over previous
#include <cuda_runtime.h>
#include <cuda_fp16.h>
#include <cstdint>

// ---------------------------------------------------------------------------
// Problem constants
// ---------------------------------------------------------------------------
static constexpr int E_  = 8;
static constexpr int H_  = 1024;
static constexpr int FF_ = 4096;
static constexpr int T_  = 32768;
static constexpr int G_  = T_ / E_;     // 4096 tokens per expert

// GEMM tiling: CTA 128x128, 8 warps (4 M x 2 N), warp tile 32x64, BK=32
// 256 threads, __launch_bounds__(256,2) -> <=128 regs -> 2 CTAs/SM.
// NSTAGE=4 + SINGLE barrier per stage: with 4 buffers, load(s+2) writes the
// (s-2)%4 buffer whose readers all finished before the sync(s-1) barrier the
// loader already passed -> trailing __syncthreads removable (race-free).
// SMEM 80KB/CTA x2 = 160KB -> 68KB L1 retained (cp.async path needs L1).
static constexpr int BM = 128;
static constexpr int BN = 128;
static constexpr int BK = 32;           // fp16 elems per K-stage
static constexpr int PITCH = 80;        // SMEM row pitch bytes (64B data + 16B pad)
static constexpr int OFF_B = BM * PITCH;                  // 10240
static constexpr int STAGE_BYTES = OFF_B + BN * PITCH;    // 20480
static constexpr int NSTAGE = 4;
static constexpr int SMEM_TOTAL = NSTAGE * STAGE_BYTES;   // 81920 (2 CTAs = 160KB)
static constexpr int NTHREADS = 256;

// ---------------------------------------------------------------------------
// Device scratch
// ---------------------------------------------------------------------------
__device__ __half g_XH[(size_t)T_ * H_];
__device__ __half g_W1H[(size_t)E_ * FF_ * H_];
__device__ __half g_W2TH[(size_t)E_ * H_ * FF_];
__device__ __half g_HH[(size_t)T_ * FF_];

// ---------------------------------------------------------------------------
// PTX helpers (family-safe: sm_80-era instructions only)
// ---------------------------------------------------------------------------
__device__ __forceinline__ uint32_t smem_u32(const void* p) {
    uint32_t a;
    asm("{ .reg .u64 t; cvta.to.shared.u64 t, %1; cvt.u32.u64 %0, t; }" : "=r"(a) : "l"(p));
    return a;
}
__device__ __forceinline__ void cp16(uint32_t dst, const void* src) {
    asm volatile("cp.async.cg.shared.global [%0], [%1], 16;" :: "r"(dst), "l"(src) : "memory");
}
#define CP_COMMIT() asm volatile("cp.async.commit_group;" ::: "memory")
#define CP_WAIT2()  asm volatile("cp.async.wait_group 2;" ::: "memory")

__device__ __forceinline__ void ldsm4(uint32_t& r0, uint32_t& r1, uint32_t& r2, uint32_t& r3,
                                      uint32_t addr) {
    asm volatile("ldmatrix.sync.aligned.m8n8.x4.shared.b16 {%0,%1,%2,%3}, [%4];"
                 : "=r"(r0), "=r"(r1), "=r"(r2), "=r"(r3) : "r"(addr));
}
__device__ __forceinline__ void mma16816(float* d, const uint32_t* a, const uint32_t* b) {
    asm volatile(
        "mma.sync.aligned.m16n8k16.row.col.f32.f16.f16.f32 "
        "{%0,%1,%2,%3}, {%4,%5,%6,%7}, {%8,%9}, {%0,%1,%2,%3};"
        : "+f"(d[0]), "+f"(d[1]), "+f"(d[2]), "+f"(d[3])
        : "r"(a[0]), "r"(a[1]), "r"(a[2]), "r"(a[3]), "r"(b[0]), "r"(b[1]));
}

__device__ __forceinline__ uint32_t pack2h(__half a, __half b) {
    __half2 p = __halves2half2(a, b);
    return *reinterpret_cast<uint32_t*>(&p);
}

// ---------------------------------------------------------------------------
// fp32 -> fp16 cast kernels
// ---------------------------------------------------------------------------
__global__ void tohalf_kernel(const float* __restrict__ in,
                              __half* __restrict__ out, int n4) {
    for (int i = blockIdx.x * blockDim.x + threadIdx.x; i < n4; i += gridDim.x * blockDim.x) {
        float4 v = reinterpret_cast<const float4*>(in)[i];
        uint2 p;
        p.x = pack2h(__float2half(v.x), __float2half(v.y));
        p.y = pack2h(__float2half(v.z), __float2half(v.w));
        reinterpret_cast<uint2*>(out)[i] = p;
    }
}

// w2 [E, FF, H] -> w2t [E, H, FF] fp16, 32x32 SMEM tile transpose
__global__ void transpose_half(const float* __restrict__ in,
                               __half* __restrict__ outh) {
    __shared__ float t[32][33];
    const int e  = blockIdx.z;
    const int h0 = blockIdx.x * 32;
    const int f0 = blockIdx.y * 32;
    const float* src = in + (size_t)e * FF_ * H_;
#pragma unroll
    for (int j = 0; j < 4; j++)
        t[threadIdx.y + j * 8][threadIdx.x] =
            src[(size_t)(f0 + threadIdx.y + j * 8) * H_ + h0 + threadIdx.x];
    __syncthreads();
    __half* dh = outh + (size_t)e * H_ * FF_;
#pragma unroll
    for (int j = 0; j < 4; j++) {
        float v = t[threadIdx.x][threadIdx.y + j * 8];
        dh[(size_t)(h0 + threadIdx.y + j * 8) * FF_ + f0 + threadIdx.x] = __float2half(v);
    }
}

// ---------------------------------------------------------------------------
// TN grouped GEMM: C[M,N] = A[M,K] @ B[N,K]^T, fp16 single-term, fp32 accum.
// CTA tile 128x128; 8 warps as 4(M) x 2(N); warp tile 32x64; mma m16n8k16.
// One __syncthreads per K-stage (4-deep ring buffer makes it safe).
// MODE 0: epilogue = relu -> fp16 store into Hc (pitch FF_)
// MODE 1: epilogue = fp32 store into Cf (pitch H_)
// ---------------------------------------------------------------------------
template <int KDIM, int MODE>
__global__ void __launch_bounds__(NTHREADS, 2)
gemm_h1(const __half* __restrict__ A, int lda,
        const __half* __restrict__ B, int ldb, int bExpStride,
        __half* __restrict__ Hc, float* __restrict__ Cf) {
    extern __shared__ char smem[];
    const uint32_t sbase = smem_u32(smem);
    const int tid  = threadIdx.x;
    const int lane = tid & 31;
    const int warp = tid >> 5;
    const int wm = warp & 3;           // 0..3 (M, 32 rows each)
    const int wn = warp >> 2;          // 0..1 (N, 64 cols each)
    const int aRow0 = blockIdx.z * G_ + blockIdx.y * BM;
    const int bRow0 = blockIdx.z * bExpStride + blockIdx.x * BN;
    const int col0  = blockIdx.x * BN;
    constexpr int S = KDIM / BK;

    float acc[2][8][4];
#pragma unroll
    for (int i = 0; i < 2; i++)
#pragma unroll
        for (int j = 0; j < 8; j++)
#pragma unroll
            for (int q = 0; q < 4; q++) acc[i][j][q] = 0.f;

    // stage loader: A 512 chunks(16B), B 512 chunks -> 4 cp16/thread
    auto load_stage = [&](int s, int buf) {
        const uint32_t st = sbase + buf * STAGE_BYTES;
        const int k0 = s * BK;
#pragma unroll
        for (int i = 0; i < 2; i++) {
            int c = tid + i * NTHREADS;
            int r = c >> 2, q = c & 3;
            uint32_t so = (uint32_t)(r * PITCH + q * 16);
            cp16(st + so,         A + (size_t)(aRow0 + r) * lda + k0 + q * 8);
            cp16(st + OFF_B + so, B + (size_t)(bRow0 + r) * ldb + k0 + q * 8);
        }
    };

    // lane-fixed parts of ldmatrix addresses
    const uint32_t aLane = (uint32_t)((wm * 32 + (lane & 15)) * PITCH + (lane >> 4) * 16);
    const uint32_t bLane = (uint32_t)((wn * 64 + (lane & 15)) * PITCH + (lane >> 4) * 16);

    load_stage(0, 0); CP_COMMIT();
    load_stage(1, 1); CP_COMMIT();

    for (int s = 0; s < S; s++) {
        if (s + 2 < S) load_stage(s + 2, (s + 2) % NSTAGE);
        CP_COMMIT();
        CP_WAIT2();
        __syncthreads();               // single barrier per stage (4-buffer ring)

        const uint32_t st = sbase + (s % NSTAGE) * STAGE_BYTES;
#pragma unroll
        for (int ks = 0; ks < 2; ks++) {               // two k16 steps per stage
            const uint32_t kOff = (uint32_t)(ks * 32); // 16 elems * 2B
            uint32_t ah[2][4], bx[8][2];
#pragma unroll
            for (int i = 0; i < 2; i++) {
                uint32_t ad = st + aLane + kOff + (uint32_t)(i * 16 * PITCH);
                ldsm4(ah[i][0], ah[i][1], ah[i][2], ah[i][3], ad);
            }
#pragma unroll
            for (int jj = 0; jj < 4; jj++) {
                uint32_t bd = st + OFF_B + bLane + kOff + (uint32_t)(jj * 16 * PITCH);
                uint32_t r0, r1, r2, r3;
                ldsm4(r0, r1, r2, r3, bd);
                bx[jj * 2 + 0][0] = r0; bx[jj * 2 + 1][0] = r1;
                bx[jj * 2 + 0][1] = r2; bx[jj * 2 + 1][1] = r3;
            }
#pragma unroll
            for (int i = 0; i < 2; i++)
#pragma unroll
                for (int j = 0; j < 8; j++) mma16816(acc[i][j], ah[i], bx[j]);
        }
    }

    // ---- epilogue (register -> global) ------------------------------------
    const int rBase = aRow0 + wm * 32 + (lane >> 2);
    const int cBase = col0 + wn * 64 + 2 * (lane & 3);
    if (MODE == 0) {
        uint32_t* gH = reinterpret_cast<uint32_t*>(Hc);
#pragma unroll
        for (int i = 0; i < 2; i++)
#pragma unroll
            for (int j = 0; j < 8; j++) {
                int r0 = rBase + i * 16;
                int c  = cBase + j * 8;
                float v0 = fmaxf(acc[i][j][0], 0.f), v1 = fmaxf(acc[i][j][1], 0.f);
                float v2 = fmaxf(acc[i][j][2], 0.f), v3 = fmaxf(acc[i][j][3], 0.f);
                size_t w0 = ((size_t)r0 * FF_ + c) >> 1;
                size_t w1 = ((size_t)(r0 + 8) * FF_ + c) >> 1;
                gH[w0] = pack2h(__float2half(v0), __float2half(v1));
                gH[w1] = pack2h(__float2half(v2), __float2half(v3));
            }
    } else {
#pragma unroll
        for (int i = 0; i < 2; i++)
#pragma unroll
            for (int j = 0; j < 8; j++) {
                int r0 = rBase + i * 16;
                int c  = cBase + j * 8;
                float2 p0 = make_float2(acc[i][j][0], acc[i][j][1]);
                float2 p1 = make_float2(acc[i][j][2], acc[i][j][3]);
                *reinterpret_cast<float2*>(&Cf[(size_t)r0 * H_ + c])       = p0;
                *reinterpret_cast<float2*>(&Cf[(size_t)(r0 + 8) * H_ + c]) = p1;
            }
    }
}

// ---------------------------------------------------------------------------
// Host launcher
// ---------------------------------------------------------------------------
extern "C" void kernel_launch(void* const* d_in, const int* in_sizes, int n_in,
                              void* d_out, int out_size) {
    (void)in_sizes; (void)n_in; (void)out_size;
    const float* x  = (const float*)d_in[0];
    const float* w1 = (const float*)d_in[1];
    const float* w2 = (const float*)d_in[2];
    float* out = (float*)d_out;

    void *xh, *w1h, *w2th, *hh;
    cudaGetSymbolAddress(&xh,  g_XH);
    cudaGetSymbolAddress(&w1h, g_W1H);
    cudaGetSymbolAddress(&w2th, g_W2TH);
    cudaGetSymbolAddress(&hh,  g_HH);

    cudaFuncSetAttribute(gemm_h1<1024, 0>,
                         cudaFuncAttributeMaxDynamicSharedMemorySize, SMEM_TOTAL);
    cudaFuncSetAttribute(gemm_h1<4096, 1>,
                         cudaFuncAttributeMaxDynamicSharedMemorySize, SMEM_TOTAL);

    // 1) fp32 -> fp16 casts
    tohalf_kernel<<<2048, 256>>>(x, (__half*)xh, T_ * H_ / 4);
    tohalf_kernel<<<2048, 256>>>(w1, (__half*)w1h, E_ * FF_ * H_ / 4);
    transpose_half<<<dim3(H_ / 32, FF_ / 32, E_), dim3(32, 8)>>>(w2, (__half*)w2th);

    // 2) GEMM1: h = relu(x @ w1^T) -> fp16; A ld=H, B ld=H, expert stride FF
    gemm_h1<1024, 0><<<dim3(FF_ / BN, G_ / BM, E_), NTHREADS, SMEM_TOTAL>>>(
        (const __half*)xh, H_,
        (const __half*)w1h, H_, FF_,
        (__half*)hh, nullptr);

    // 3) GEMM2: out = h @ w2 (w2 pre-transposed -> TN); A ld=FF, B ld=FF, stride H
    gemm_h1<4096, 1><<<dim3(H_ / BN, G_ / BM, E_), NTHREADS, SMEM_TOTAL>>>(
        (const __half*)hh, FF_,
        (const __half*)w2th, FF_, H_,
        nullptr, out);
}